// round 9
// baseline (speedup 1.0000x reference)
#include <cuda_runtime.h>

// Problem constants
#define HID     32
#define TSTEPS  512
#define BATCH   4096
#define NB      4                 // batch chains per warp
#define WPB     8                 // warps per block
#define THREADS (WPB * 32)        // 256
#define NBLOCKS (BATCH / (NB * WPB))  // 128
#define FOUT    20

typedef unsigned long long u64;

// ---- packed f32x2 helpers (Blackwell fp32x2 pipe) ----
__device__ __forceinline__ u64 f2fma(u64 a, u64 b, u64 c) {
    u64 d;
    asm("fma.rn.f32x2 %0, %1, %2, %3;" : "=l"(d) : "l"(a), "l"(b), "l"(c));
    return d;
}
__device__ __forceinline__ u64 pack2(float lo, float hi) {
    u64 d;
    asm("mov.b64 %0, {%1, %2};" : "=l"(d) : "f"(lo), "f"(hi));
    return d;
}
__device__ __forceinline__ void unpack2(u64 v, float& lo, float& hi) {
    asm("mov.b64 {%0, %1}, %2;" : "=f"(lo), "=f"(hi) : "l"(v));
}

// ---- fast-but-accurate activations (~2 ulp via EX2 + RCP) ----
__device__ __forceinline__ float sigmoid_(float x) {
    float e = __expf(-x);                       // MUFU.EX2 path
    return __fdividef(1.0f, 1.0f + e);          // MUFU.RCP path
}
__device__ __forceinline__ float tanh_(float x) {
    float ax = fabsf(x);
    float e  = __expf(-2.0f * ax);              // in (0,1], no overflow
    float r  = __fdividef(1.0f - e, 1.0f + e);  // tanh(|x|)
    return __int_as_float(__float_as_int(r) |
                          (__float_as_int(x) & 0x80000000u));
}

// SMEM layout (floats):
//   Wp1 : [32][32][4]  k-major, gate-interleaved W_hh1      (4096 f, 16KB)
//   Wp2 : [64][32][4]  k<32: W_ih2, k>=32: W_hh2            (8192 f, 32KB)
//   per warp (640 f): hdup[64][8]  duplicated h (h1 slots 0..31, h2 slots 32..63)
//                     h2pl[32][4]  plain h2 (for output matvec)
#define SMEM_FLOATS (32*128 + 64*128 + WPB * 640)   // 17408 floats = 69632 B

__global__ void __launch_bounds__(THREADS)
lstm_seq_kernel(const float* __restrict__ x,
                const float* __restrict__ Wih1, const float* __restrict__ Whh1,
                const float* __restrict__ bih1, const float* __restrict__ bhh1,
                const float* __restrict__ Wih2, const float* __restrict__ Whh2,
                const float* __restrict__ bih2, const float* __restrict__ bhh2,
                const float* __restrict__ Wout, const float* __restrict__ bout,
                float* __restrict__ out)
{
    extern __shared__ float sm[];
    float* Wp1 = sm;                 // 4096
    float* Wp2 = sm + 32 * 128;      // 8192
    float* hreg = Wp2 + 64 * 128;    // WPB * 640

    const int tid = threadIdx.x;
    const int wid = tid >> 5;
    const int L   = tid & 31;

    // ---- cooperative weight packing: Wp[k*128 + l*4 + g] = W[(g*32+l)*32 + k] ----
    for (int i = tid; i < 32 * 128; i += THREADS) {
        int k = i >> 7, r = i & 127, g = r & 3, l = r >> 2;
        Wp1[i] = Whh1[(g * 32 + l) * 32 + k];
    }
    for (int i = tid; i < 64 * 128; i += THREADS) {
        int k = i >> 7, r = i & 127, g = r & 3, l = r >> 2;
        Wp2[i] = (k < 32) ? Wih2[(g * 32 + l) * 32 + k]
                          : Whh2[(g * 32 + l) * 32 + (k - 32)];
    }
    __syncthreads();

    float* hdup = hreg + wid * 640;  // [64][8]
    float* h2pl = hdup + 512;        // [32][4]

    // ---- per-lane register-resident constants ----
    // W_ih1 rows (g*32+L), 2 input cols, packed over gate pairs
    u64 wxIF0 = pack2(Wih1[(0 * 32 + L) * 2 + 0], Wih1[(1 * 32 + L) * 2 + 0]);
    u64 wxIF1 = pack2(Wih1[(0 * 32 + L) * 2 + 1], Wih1[(1 * 32 + L) * 2 + 1]);
    u64 wxGO0 = pack2(Wih1[(2 * 32 + L) * 2 + 0], Wih1[(3 * 32 + L) * 2 + 0]);
    u64 wxGO1 = pack2(Wih1[(2 * 32 + L) * 2 + 1], Wih1[(3 * 32 + L) * 2 + 1]);
    u64 b1IF = pack2(bih1[L]      + bhh1[L],      bih1[32 + L] + bhh1[32 + L]);
    u64 b1GO = pack2(bih1[64 + L] + bhh1[64 + L], bih1[96 + L] + bhh1[96 + L]);
    u64 b2IF = pack2(bih2[L]      + bhh2[L],      bih2[32 + L] + bhh2[32 + L]);
    u64 b2GO = pack2(bih2[64 + L] + bhh2[64 + L], bih2[96 + L] + bhh2[96 + L]);

    const int orow = (L < FOUT) ? L : 0;
    float wo[32];
#pragma unroll
    for (int k = 0; k < 32; ++k) wo[k] = Wout[orow * 32 + k];
    const u64 bo2 = pack2(bout[orow], bout[orow]);

    // ---- state init ----
    float c1[NB], c2[NB];
#pragma unroll
    for (int nb = 0; nb < NB; ++nb) { c1[nb] = 0.0f; c2[nb] = 0.0f; }

    float4 z4 = make_float4(0.f, 0.f, 0.f, 0.f);
    ((float4*)(hdup + L * 8))[0] = z4;          // h1 dup
    ((float4*)(hdup + L * 8))[1] = z4;
    ((float4*)(hdup + (32 + L) * 8))[0] = z4;   // h2 dup
    ((float4*)(hdup + (32 + L) * 8))[1] = z4;
    ((float4*)(h2pl + L * 4))[0] = z4;          // h2 plain
    __syncwarp();

    const int warp_g = blockIdx.x * WPB + wid;
    const int b0 = warp_g * NB;
    const float2* xp = (const float2*)x;        // index: b*TSTEPS + t

    float2 xc[NB];
#pragma unroll
    for (int nb = 0; nb < NB; ++nb) xc[nb] = xp[(b0 + nb) * TSTEPS];

#pragma unroll 1
    for (int t = 0; t < TSTEPS; ++t) {
        // ===== layer 1: gates = W_ih1 x + W_hh1 h1 + b1 =====
        u64 aIF[NB], aGO[NB];
#pragma unroll
        for (int nb = 0; nb < NB; ++nb) {
            u64 x0 = pack2(xc[nb].x, xc[nb].x);
            u64 x1 = pack2(xc[nb].y, xc[nb].y);
            aIF[nb] = f2fma(wxIF0, x0, f2fma(wxIF1, x1, b1IF));
            aGO[nb] = f2fma(wxGO0, x0, f2fma(wxGO1, x1, b1GO));
        }
        // prefetch next step's x (overlaps with the matvec below)
        {
            int tn = (t + 1 < TSTEPS) ? t + 1 : t;
#pragma unroll
            for (int nb = 0; nb < NB; ++nb) xc[nb] = xp[(b0 + nb) * TSTEPS + tn];
        }

#pragma unroll
        for (int k = 0; k < 32; ++k) {
            ulonglong2 w  = ((const ulonglong2*)Wp1)[k * 32 + L];  // {wi,wf},{wg,wo}
            ulonglong2 ha = ((const ulonglong2*)hdup)[k * 2 + 0];  // {h0,h0},{h1,h1}
            ulonglong2 hb = ((const ulonglong2*)hdup)[k * 2 + 1];  // {h2,h2},{h3,h3}
            aIF[0] = f2fma(w.x, ha.x, aIF[0]); aGO[0] = f2fma(w.y, ha.x, aGO[0]);
            aIF[1] = f2fma(w.x, ha.y, aIF[1]); aGO[1] = f2fma(w.y, ha.y, aGO[1]);
            aIF[2] = f2fma(w.x, hb.x, aIF[2]); aGO[2] = f2fma(w.y, hb.x, aGO[2]);
            aIF[3] = f2fma(w.x, hb.y, aIF[3]); aGO[3] = f2fma(w.y, hb.y, aGO[3]);
        }

        float h1n[NB];
#pragma unroll
        for (int nb = 0; nb < NB; ++nb) {
            float gi, gf, gg, go;
            unpack2(aIF[nb], gi, gf);
            unpack2(aGO[nb], gg, go);
            float ii = sigmoid_(gi), ff = sigmoid_(gf);
            float g_ = tanh_(gg),    oo = sigmoid_(go);
            c1[nb]  = ff * c1[nb] + ii * g_;
            h1n[nb] = oo * tanh_(c1[nb]);
        }
        __syncwarp();
        ((float4*)(hdup + L * 8))[0] = make_float4(h1n[0], h1n[0], h1n[1], h1n[1]);
        ((float4*)(hdup + L * 8))[1] = make_float4(h1n[2], h1n[2], h1n[3], h1n[3]);
        __syncwarp();

        // ===== layer 2: gates = W_ih2 h1_new + W_hh2 h2_old + b2 (fused k=0..63) =====
#pragma unroll
        for (int nb = 0; nb < NB; ++nb) { aIF[nb] = b2IF; aGO[nb] = b2GO; }
#pragma unroll
        for (int k = 0; k < 64; ++k) {
            ulonglong2 w  = ((const ulonglong2*)Wp2)[k * 32 + L];
            ulonglong2 ha = ((const ulonglong2*)hdup)[k * 2 + 0];
            ulonglong2 hb = ((const ulonglong2*)hdup)[k * 2 + 1];
            aIF[0] = f2fma(w.x, ha.x, aIF[0]); aGO[0] = f2fma(w.y, ha.x, aGO[0]);
            aIF[1] = f2fma(w.x, ha.y, aIF[1]); aGO[1] = f2fma(w.y, ha.y, aGO[1]);
            aIF[2] = f2fma(w.x, hb.x, aIF[2]); aGO[2] = f2fma(w.y, hb.x, aGO[2]);
            aIF[3] = f2fma(w.x, hb.y, aIF[3]); aGO[3] = f2fma(w.y, hb.y, aGO[3]);
        }

        float h2n[NB];
#pragma unroll
        for (int nb = 0; nb < NB; ++nb) {
            float gi, gf, gg, go;
            unpack2(aIF[nb], gi, gf);
            unpack2(aGO[nb], gg, go);
            float ii = sigmoid_(gi), ff = sigmoid_(gf);
            float g_ = tanh_(gg),    oo = sigmoid_(go);
            c2[nb]  = ff * c2[nb] + ii * g_;
            h2n[nb] = oo * tanh_(c2[nb]);
        }
        __syncwarp();
        ((float4*)(hdup + (32 + L) * 8))[0] = make_float4(h2n[0], h2n[0], h2n[1], h2n[1]);
        ((float4*)(hdup + (32 + L) * 8))[1] = make_float4(h2n[2], h2n[2], h2n[3], h2n[3]);
        ((float4*)(h2pl + L * 4))[0]        = make_float4(h2n[0], h2n[1], h2n[2], h2n[3]);
        __syncwarp();

        // ===== output: out = W_out h2_new + b_out (lanes 0..19 own one row) =====
        u64 o01 = bo2, o23 = bo2;
#pragma unroll
        for (int k = 0; k < 32; ++k) {
            ulonglong2 h = ((const ulonglong2*)h2pl)[k];   // {h0,h1},{h2,h3}
            u64 ws = pack2(wo[k], wo[k]);
            o01 = f2fma(ws, h.x, o01);
            o23 = f2fma(ws, h.y, o23);
        }
        if (L < FOUT) {
            float o0, o1, o2, o3;
            unpack2(o01, o0, o1);
            unpack2(o23, o2, o3);
            size_t ob = ((size_t)b0 * TSTEPS + t) * FOUT + L;
            const size_t stride = (size_t)TSTEPS * FOUT;
            out[ob]              = o0;
            out[ob + stride]     = o1;
            out[ob + 2 * stride] = o2;
            out[ob + 3 * stride] = o3;
        }
    }
}

extern "C" void kernel_launch(void* const* d_in, const int* in_sizes, int n_in,
                              void* d_out, int out_size) {
    const float* x    = (const float*)d_in[0];
    const float* Wih1 = (const float*)d_in[1];
    const float* Whh1 = (const float*)d_in[2];
    const float* bih1 = (const float*)d_in[3];
    const float* bhh1 = (const float*)d_in[4];
    const float* Wih2 = (const float*)d_in[5];
    const float* Whh2 = (const float*)d_in[6];
    const float* bih2 = (const float*)d_in[7];
    const float* bhh2 = (const float*)d_in[8];
    const float* Wout = (const float*)d_in[9];
    const float* bo   = (const float*)d_in[10];

    size_t smem = SMEM_FLOATS * sizeof(float);  // 69632 B (> 48KB static limit)
    cudaFuncSetAttribute(lstm_seq_kernel,
                         cudaFuncAttributeMaxDynamicSharedMemorySize, (int)smem);

    lstm_seq_kernel<<<NBLOCKS, THREADS, smem>>>(
        x, Wih1, Whh1, bih1, bhh1, Wih2, Whh2, bih2, bhh2, Wout, bo,
        (float*)d_out);
}